// round 12
// baseline (speedup 1.0000x reference)
#include <cuda_runtime.h>

#define NB 512      // batch
#define NT 1024     // time steps
#define HID 64      // hidden
#define NG 192      // 3 * HID gates

// Scratch (static __device__ arrays; allocation-free per harness rules)
__device__ float g_xgA[(size_t)NT * NB * NG];  // xg for even layers (0,2,4)
__device__ float g_xgB[(size_t)NT * NB * NG];  // xg for odd layers (1,3)
__device__ float g_h0[(size_t)NT * NB * HID];  // layer outputs ping
__device__ float g_h1[(size_t)NT * NB * HID];  // pong

__device__ __forceinline__ float sigf(float x) {
    return __fdividef(1.f, 1.f + __expf(-x));
}
__device__ __forceinline__ float tanh_(float x) {
    return fmaf(2.f, sigf(2.f * x), -1.f);
}

// packed fp32x2 ops
__device__ __forceinline__ unsigned long long ffma2(unsigned long long a,
                                                    unsigned long long b,
                                                    unsigned long long c) {
    unsigned long long d;
    asm("fma.rn.f32x2 %0, %1, %2, %3;" : "=l"(d) : "l"(a), "l"(b), "l"(c));
    return d;
}
__device__ __forceinline__ unsigned long long fadd2(unsigned long long a,
                                                    unsigned long long b) {
    unsigned long long d;
    asm("add.rn.f32x2 %0, %1, %2;" : "=l"(d) : "l"(a), "l"(b));
    return d;
}
__device__ __forceinline__ float f2sum(unsigned long long v) {
    return __uint_as_float((unsigned)v) + __uint_as_float((unsigned)(v >> 32));
}

// ---------------------------------------------------------------------------
// Layer-0 input GEMM: xg[t][b][g] = b0[g] + x[b][t][:].w0[g][:]  (input dim 5)
// ---------------------------------------------------------------------------
__global__ void k_inp0(const float* __restrict__ x,
                       const float* __restrict__ w0,
                       const float* __restrict__ b0,
                       float* __restrict__ xg) {
    const int g = threadIdx.x;                 // 0..191
    const int row0 = blockIdx.x * 32;          // row = t*NB + b
    __shared__ float xs[32][5];

    float w[5];
#pragma unroll
    for (int i = 0; i < 5; i++) w[i] = w0[g * 5 + i];
    const float bias = b0[g];

    for (int i = g; i < 32 * 5; i += NG) {
        int r = i / 5, c = i % 5;
        int row = row0 + r;
        int t = row / NB, b = row % NB;        // xg rows are t-major
        xs[r][c] = x[((size_t)b * NT + t) * 5 + c];
    }
    __syncthreads();

#pragma unroll 4
    for (int r = 0; r < 32; r++) {
        float acc = bias;
#pragma unroll
        for (int c = 0; c < 5; c++) acc += w[c] * xs[r][c];
        xg[((size_t)(row0 + r)) * NG + g] = acc;
    }
}

// ---------------------------------------------------------------------------
// Layers 1..4 input GEMM, split-K over lane pairs. 384 threads, 64 rows/block.
// (unchanged from R10 — proven)
// ---------------------------------------------------------------------------
__global__ __launch_bounds__(384, 2)
void k_inp(const float* __restrict__ hin,
           const float* __restrict__ w_ih,
           const float* __restrict__ b_ih,
           float* __restrict__ xg) {
    const int tid = threadIdx.x;
    const int g = tid >> 1;
    const int kh = tid & 1;
    const size_t row0 = (size_t)blockIdx.x * 64;
    __shared__ __align__(16) float hs[64][HID];

    unsigned long long w2[16];
    const ulonglong2* wp = (const ulonglong2*)(w_ih + (size_t)g * HID);
#pragma unroll
    for (int k = 0; k < 8; k++) {
        ulonglong2 v = wp[2 * k + kh];
        w2[2 * k] = v.x; w2[2 * k + 1] = v.y;
    }
    const float bias = b_ih[g];

    const float4* src = (const float4*)(hin + row0 * HID);
    float4* dst = (float4*)hs;
    for (int i = tid; i < 1024; i += 384) dst[i] = src[i];
    __syncthreads();

#pragma unroll 1
    for (int grp = 0; grp < 16; grp++) {
        const int base = grp * 4;
        unsigned long long ax[4], ay[4];
#pragma unroll
        for (int i = 0; i < 4; i++) { ax[i] = 0; ay[i] = 0; }
#pragma unroll
        for (int k = 0; k < 8; k++) {
            const int c = 2 * k + kh;
#pragma unroll
            for (int i = 0; i < 4; i++) {
                ulonglong2 v = ((const ulonglong2*)hs[base + i])[c];
                ax[i] = ffma2(w2[2 * k],     v.x, ax[i]);
                ay[i] = ffma2(w2[2 * k + 1], v.y, ay[i]);
            }
        }
        float s[4];
#pragma unroll
        for (int i = 0; i < 4; i++) {
            float h = f2sum(fadd2(ax[i], ay[i]));
            s[i] = h + __shfl_xor_sync(0xFFFFFFFFu, h, 1);
        }
#pragma unroll
        for (int i = 0; i < 2; i++) {
            int r = base + 2 * kh + i;
            xg[(row0 + r) * NG + g] = bias + s[2 * kh + i];
        }
    }
}

// ---------------------------------------------------------------------------
// Recurrent scan: all 3 gates per thread, lane-pair K-split, ONE barrier/step.
// 512 blocks x 128 threads (1 batch row per CTA), 4 CTAs/SM.
// Thread (j, kh): holds half (chunks 2k+kh) of w_hh rows j, 64+j, 128+j.
// 8 LDS.128 of the h half feed all 48 FFMA2. 3 shfl_xor(1) give both lanes
// the full r/z/n preacts; gate math + h update fully thread-local.
// Double-buffered h_sh: single __syncthreads per step (4 warps only).
// Gate order (torch): r=[0:64), z=[64:128), n=[128:192).
// ---------------------------------------------------------------------------
__global__ __launch_bounds__(128, 4)
void k_scan(const float* __restrict__ w_hh,
            const float* __restrict__ b_hh,
            const float* __restrict__ xg,
            float* __restrict__ hout, int store_all) {
    const int tid = threadIdx.x;
    const int kh = tid & 1;
    const int j = tid >> 1;          // 0..63
    const int b = blockIdx.x;        // one batch row per CTA

    __shared__ __align__(16) float h_sh[2][HID];   // [phase][j]

    // weights: half of rows j (r), 64+j (z), 128+j (n); chunks c = 2k+kh
    unsigned long long wr[16], wz[16], wn[16];
    {
        const ulonglong2* pr = (const ulonglong2*)(w_hh + (size_t)j * HID);
        const ulonglong2* pz = (const ulonglong2*)(w_hh + (size_t)(64 + j) * HID);
        const ulonglong2* pn = (const ulonglong2*)(w_hh + (size_t)(128 + j) * HID);
#pragma unroll
        for (int k = 0; k < 8; k++) {
            ulonglong2 vr = pr[2 * k + kh];
            ulonglong2 vz = pz[2 * k + kh];
            ulonglong2 vn = pn[2 * k + kh];
            wr[2 * k] = vr.x; wr[2 * k + 1] = vr.y;
            wz[2 * k] = vz.x; wz[2 * k + 1] = vz.y;
            wn[2 * k] = vn.x; wn[2 * k + 1] = vn.y;
        }
    }
    const float br = b_hh[j], bz = b_hh[64 + j], bn = b_hh[128 + j];

    if (tid < HID) { h_sh[0][tid] = 0.f; h_sh[1][tid] = 0.f; }
    float hprev = 0.f;
    __syncthreads();

    // xg for this (b, j): gates j, 64+j, 128+j
    const float* xb = xg + (size_t)b * NG;
    float xr = xb[j], xz = xb[64 + j], xn = xb[128 + j];

    for (int t = 0; t < NT; t++) {
        // prefetch next step's xg
        float pxr = 0.f, pxz = 0.f, pxn = 0.f;
        if (t + 1 < NT) {
            const float* q = xg + ((size_t)(t + 1) * NB + b) * NG;
            pxr = q[j]; pxz = q[64 + j]; pxn = q[128 + j];
        }

        const int p = t & 1;
        unsigned long long ar0 = 0, ar1 = 0, az0 = 0, az1 = 0, an0 = 0, an1 = 0;
        const ulonglong2* hv = (const ulonglong2*)h_sh[p];
#pragma unroll
        for (int k = 0; k < 8; k++) {
            ulonglong2 v = hv[2 * k + kh];      // 8 LDS.128, reused by 3 gates
            ar0 = ffma2(wr[2 * k], v.x, ar0); ar1 = ffma2(wr[2 * k + 1], v.y, ar1);
            az0 = ffma2(wz[2 * k], v.x, az0); az1 = ffma2(wz[2 * k + 1], v.y, az1);
            an0 = ffma2(wn[2 * k], v.x, an0); an1 = ffma2(wn[2 * k + 1], v.y, an1);
        }
        float hr = f2sum(fadd2(ar0, ar1));
        float hz = f2sum(fadd2(az0, az1));
        float hd = f2sum(fadd2(an0, an1));
        hr += __shfl_xor_sync(0xFFFFFFFFu, hr, 1);   // combine K halves
        hz += __shfl_xor_sync(0xFFFFFFFFu, hz, 1);
        hd += __shfl_xor_sync(0xFFFFFFFFu, hd, 1);

        // gates fully local (both lanes compute identically)
        float rg = sigf(xr + br + hr);
        float zg = sigf(xz + bz + hz);
        float ng = tanh_(xn + rg * (bn + hd));
        float hn = ng + zg * (hprev - ng);
        hprev = hn;

        if (kh == 0) h_sh[p ^ 1][j] = hn;            // publish for next step
        if (kh == 1 && (store_all || t == NT - 1))
            hout[((size_t)t * NB + b) * HID + j] = hn;
        __syncthreads();                             // single barrier per step

        xr = pxr; xz = pxz; xn = pxn;
    }
}

// ---------------------------------------------------------------------------
// Final FC on last timestep: out[b] = h[T-1][b][:] . w_fc + b_fc
// ---------------------------------------------------------------------------
__global__ void k_fc(const float* __restrict__ hin,
                     const float* __restrict__ w_fc,
                     const float* __restrict__ b_fc,
                     float* __restrict__ out) {
    int b = blockIdx.x * blockDim.x + threadIdx.x;
    if (b >= NB) return;
    const float* hp = hin + ((size_t)(NT - 1) * NB + b) * HID;
    float acc = b_fc[0];
#pragma unroll
    for (int k = 0; k < HID; k++) acc += hp[k] * w_fc[k];
    out[b] = acc;
}

// ---------------------------------------------------------------------------
extern "C" void kernel_launch(void* const* d_in, const int* in_sizes, int n_in,
                              void* d_out, int out_size) {
    const float* x     = (const float*)d_in[0];
    const float* w_ih0 = (const float*)d_in[1];
    const float* w_hh0 = (const float*)d_in[2];
    const float* b_ih0 = (const float*)d_in[3];
    const float* b_hh0 = (const float*)d_in[4];
    const float* w_ih  = (const float*)d_in[5];   // [4][192][64]
    const float* w_hh  = (const float*)d_in[6];   // [4][192][64]
    const float* b_ih  = (const float*)d_in[7];   // [4][192]
    const float* b_hh  = (const float*)d_in[8];   // [4][192]
    const float* w_fc  = (const float*)d_in[9];
    const float* b_fc  = (const float*)d_in[10];
    float* out = (float*)d_out;

    float *hA, *hB, *xgA, *xgB;
    cudaGetSymbolAddress((void**)&hA, g_h0);
    cudaGetSymbolAddress((void**)&hB, g_h1);
    cudaGetSymbolAddress((void**)&xgA, g_xgA);
    cudaGetSymbolAddress((void**)&xgB, g_xgB);

    // Layer 0
    k_inp0<<<(NT * NB) / 32, NG>>>(x, w_ih0, b_ih0, xgA);
    k_scan<<<NB, 128>>>(w_hh0, b_hh0, xgA, hA, 1);

    // Layers 1..4 (serial on the capture stream)
    float* hin = hA;
    float* hou = hB;
    for (int L = 0; L < 4; L++) {
        int last = (L == 3);
        float* xg = (L & 1) ? xgA : xgB;
        k_inp<<<(NT * NB) / 64, 384>>>(hin, w_ih + (size_t)L * NG * HID,
                                       b_ih + L * NG, xg);
        k_scan<<<NB, 128>>>(w_hh + (size_t)L * NG * HID, b_hh + L * NG,
                            xg, hou, !last);
        float* tmp = hin; hin = hou; hou = tmp;
    }

    // FC head on last timestep (hin holds the last layer's output)
    k_fc<<<2, 256>>>(hin, w_fc, b_fc, out);
}

// round 13
// speedup vs baseline: 1.3910x; 1.3910x over previous
#include <cuda_runtime.h>

#define NB 512      // batch
#define NT 1024     // time steps
#define HID 64      // hidden
#define NG 192      // 3 * HID gates

// Scratch (static __device__ arrays; allocation-free per harness rules)
__device__ float g_xgA[(size_t)NT * NB * NG];  // xg for even layers (0,2,4)
__device__ float g_xgB[(size_t)NT * NB * NG];  // xg for odd layers (1,3)
__device__ float g_h0[(size_t)NT * NB * HID];  // layer outputs ping
__device__ float g_h1[(size_t)NT * NB * HID];  // pong

__device__ __forceinline__ float sigf(float x) {
    return __fdividef(1.f, 1.f + __expf(-x));
}
__device__ __forceinline__ float tanh_(float x) {
    return fmaf(2.f, sigf(2.f * x), -1.f);
}

// packed fp32x2 ops
__device__ __forceinline__ unsigned long long ffma2(unsigned long long a,
                                                    unsigned long long b,
                                                    unsigned long long c) {
    unsigned long long d;
    asm("fma.rn.f32x2 %0, %1, %2, %3;" : "=l"(d) : "l"(a), "l"(b), "l"(c));
    return d;
}
__device__ __forceinline__ unsigned long long fadd2(unsigned long long a,
                                                    unsigned long long b) {
    unsigned long long d;
    asm("add.rn.f32x2 %0, %1, %2;" : "=l"(d) : "l"(a), "l"(b));
    return d;
}
__device__ __forceinline__ float f2sum(unsigned long long v) {
    return __uint_as_float((unsigned)v) + __uint_as_float((unsigned)(v >> 32));
}

// tf32 helpers
__device__ __forceinline__ unsigned cvt_tf32(float x) {
    unsigned u;
    asm("cvt.rna.tf32.f32 %0, %1;" : "=r"(u) : "f"(x));
    return u;
}
__device__ __forceinline__ void mma_tf32(float* d,
                                         unsigned a0, unsigned a1,
                                         unsigned a2, unsigned a3,
                                         unsigned b0, unsigned b1) {
    asm("mma.sync.aligned.m16n8k8.row.col.f32.tf32.tf32.f32 "
        "{%0,%1,%2,%3}, {%4,%5,%6,%7}, {%8,%9}, {%0,%1,%2,%3};"
        : "+f"(d[0]), "+f"(d[1]), "+f"(d[2]), "+f"(d[3])
        : "r"(a0), "r"(a1), "r"(a2), "r"(a3), "r"(b0), "r"(b1));
}

// ---------------------------------------------------------------------------
// Layer-0 input GEMM (scalar fp32): xg[t][b][g] = b0[g] + x[b][t][:].w0[g][:]
// ---------------------------------------------------------------------------
__global__ void k_inp0(const float* __restrict__ x,
                       const float* __restrict__ w0,
                       const float* __restrict__ b0,
                       float* __restrict__ xg) {
    const int g = threadIdx.x;                 // 0..191
    const int row0 = blockIdx.x * 32;          // row = t*NB + b
    __shared__ float xs[32][5];

    float w[5];
#pragma unroll
    for (int i = 0; i < 5; i++) w[i] = w0[g * 5 + i];
    const float bias = b0[g];

    for (int i = g; i < 32 * 5; i += NG) {
        int r = i / 5, c = i % 5;
        int row = row0 + r;
        int t = row / NB, b = row % NB;        // xg rows are t-major
        xs[r][c] = x[((size_t)b * NT + t) * 5 + c];
    }
    __syncthreads();

#pragma unroll 4
    for (int r = 0; r < 32; r++) {
        float acc = bias;
#pragma unroll
        for (int c = 0; c < 5; c++) acc += w[c] * xs[r][c];
        xg[((size_t)(row0 + r)) * NG + g] = acc;
    }
}

// ---------------------------------------------------------------------------
// Layers 1..4 input GEMM, TF32 tensor cores.
// OUT[row][g] = b[g] + H[row][:]. W[g][:]  via mma.m16n8k8.row.col.
// CTA: 384 threads = 12 warps; warp w owns gates [16w, 16w+16) (two n=8
// blocks, B-frags register-resident for all 8 k-blocks). CTA tile: 128 rows.
// H tile staged in smem pre-converted to tf32; 68-float row pad -> A-frag
// LDS hits 32 distinct banks.
// ---------------------------------------------------------------------------
__global__ __launch_bounds__(384, 2)
void k_inp_tc(const float* __restrict__ hin,
              const float* __restrict__ w_ih,
              const float* __restrict__ b_ih,
              float* __restrict__ xg) {
    const int tid = threadIdx.x;
    const int wid = tid >> 5;        // 0..11
    const int lane = tid & 31;
    const int grp = lane >> 2;       // 0..7
    const int tig = lane & 3;        // 0..3
    const size_t row0 = (size_t)blockIdx.x * 128;

    __shared__ __align__(16) float Hs[128][68];

    // B fragments + biases (once per kernel)
    unsigned wb[2][8][2];
    float bias0[2], bias1[2];
#pragma unroll
    for (int gh = 0; gh < 2; gh++) {
        const int gbase = wid * 16 + gh * 8;
        const float* wrow = w_ih + (size_t)(gbase + grp) * HID;
#pragma unroll
        for (int kb = 0; kb < 8; kb++) {
            wb[gh][kb][0] = cvt_tf32(wrow[kb * 8 + tig]);
            wb[gh][kb][1] = cvt_tf32(wrow[kb * 8 + tig + 4]);
        }
        bias0[gh] = b_ih[gbase + 2 * tig];
        bias1[gh] = b_ih[gbase + 2 * tig + 1];
    }

    // stage H tile (128 x 64), converting to tf32 bit patterns
    for (int i = tid; i < 128 * 16; i += 384) {
        const int r = i >> 4, c4 = (i & 15) * 4;
        float4 v = ((const float4*)(hin + (row0 + r) * HID))[i & 15];
        Hs[r][c4 + 0] = __uint_as_float(cvt_tf32(v.x));
        Hs[r][c4 + 1] = __uint_as_float(cvt_tf32(v.y));
        Hs[r][c4 + 2] = __uint_as_float(cvt_tf32(v.z));
        Hs[r][c4 + 3] = __uint_as_float(cvt_tf32(v.w));
    }
    __syncthreads();

#pragma unroll 1
    for (int rt = 0; rt < 8; rt++) {
        const int r0 = rt * 16;
        float acc[2][4];
#pragma unroll
        for (int gh = 0; gh < 2; gh++) {
            acc[gh][0] = bias0[gh]; acc[gh][1] = bias1[gh];
            acc[gh][2] = bias0[gh]; acc[gh][3] = bias1[gh];
        }
#pragma unroll
        for (int kb = 0; kb < 8; kb++) {
            const int kc = kb * 8 + tig;
            unsigned a0 = __float_as_uint(Hs[r0 + grp][kc]);
            unsigned a1 = __float_as_uint(Hs[r0 + grp + 8][kc]);
            unsigned a2 = __float_as_uint(Hs[r0 + grp][kc + 4]);
            unsigned a3 = __float_as_uint(Hs[r0 + grp + 8][kc + 4]);
            mma_tf32(acc[0], a0, a1, a2, a3, wb[0][kb][0], wb[0][kb][1]);
            mma_tf32(acc[1], a0, a1, a2, a3, wb[1][kb][0], wb[1][kb][1]);
        }
#pragma unroll
        for (int gh = 0; gh < 2; gh++) {
            const int gcol = wid * 16 + gh * 8 + 2 * tig;
            float2* o0 = (float2*)(xg + (row0 + r0 + grp) * NG + gcol);
            *o0 = make_float2(acc[gh][0], acc[gh][1]);
            float2* o1 = (float2*)(xg + (row0 + r0 + grp + 8) * NG + gcol);
            *o1 = make_float2(acc[gh][2], acc[gh][3]);
        }
    }
}

// ---------------------------------------------------------------------------
// Recurrent scan (R10, proven 627us): split-K over lane pairs. 256 blocks x
// 384 threads, 2 batch rows/block, 2 CTAs/SM. Gate order: r, z, n.
// ---------------------------------------------------------------------------
__global__ __launch_bounds__(384, 2)
void k_scan(const float* __restrict__ w_hh,
            const float* __restrict__ b_hh,
            const float* __restrict__ xg,
            float* __restrict__ hout, int store_all) {
    const int tid = threadIdx.x;
    const int g = tid >> 1;          // gate 0..191
    const int kh = tid & 1;          // K half == owned batch row
    const int j = g & 63;
    const int b0 = blockIdx.x * 2;

    __shared__ __align__(16) float h_sh[2][HID];
    __shared__ float rz_sh[2][2][HID];   // [r|z][row][j]

    unsigned long long w2[16];
    const ulonglong2* wp = (const ulonglong2*)(w_hh + (size_t)g * HID);
#pragma unroll
    for (int k = 0; k < 8; k++) {
        ulonglong2 v = wp[2 * k + kh];
        w2[2 * k] = v.x; w2[2 * k + 1] = v.y;
    }
    const float bias = b_hh[g];

    if (tid < 2 * HID) ((float*)h_sh)[tid] = 0.f;
    __syncthreads();

    const float* xb = xg + ((size_t)b0 + kh) * NG + g;
    float xc = xb[0];

    for (int t = 0; t < NT; t++) {
        float xn = 0.f;
        if (t + 1 < NT) xn = xb[(size_t)(t + 1) * NB * NG];

        unsigned long long a0x = 0, a0y = 0, a1x = 0, a1y = 0;
        const ulonglong2* h0 = (const ulonglong2*)h_sh[0];
        const ulonglong2* h1 = (const ulonglong2*)h_sh[1];
#pragma unroll
        for (int k = 0; k < 8; k++) {
            const int c = 2 * k + kh;
            ulonglong2 v0 = h0[c], v1 = h1[c];
            a0x = ffma2(w2[2 * k],     v0.x, a0x);
            a0y = ffma2(w2[2 * k + 1], v0.y, a0y);
            a1x = ffma2(w2[2 * k],     v1.x, a1x);
            a1y = ffma2(w2[2 * k + 1], v1.y, a1y);
        }
        float s0 = f2sum(fadd2(a0x, a0y));
        float s1 = f2sum(fadd2(a1x, a1y));
        s0 += __shfl_xor_sync(0xFFFFFFFFu, s0, 1);
        s1 += __shfl_xor_sync(0xFFFFFFFFu, s1, 1);
        const float sown = bias + (kh ? s1 : s0);

        if (g < 128) {
            const int which = g >> 6;   // 0 = r, 1 = z
            rz_sh[which][kh][j] = sigf(xc + sown);
        }
        __syncthreads();                 // rz ready; dot reads of h_sh done

        if (g >= 128) {
            float n = tanh_(xc + rz_sh[0][kh][j] * sown);
            float z = rz_sh[1][kh][j];
            float hp = h_sh[kh][j];
            float hn = n + z * (hp - n);
            h_sh[kh][j] = hn;
            if (store_all || t == NT - 1)
                hout[((size_t)t * NB + b0 + kh) * HID + j] = hn;
        }
        __syncthreads();                 // h_sh updated for next step
        xc = xn;
    }
}

// ---------------------------------------------------------------------------
// Final FC on last timestep: out[b] = h[T-1][b][:] . w_fc + b_fc
// ---------------------------------------------------------------------------
__global__ void k_fc(const float* __restrict__ hin,
                     const float* __restrict__ w_fc,
                     const float* __restrict__ b_fc,
                     float* __restrict__ out) {
    int b = blockIdx.x * blockDim.x + threadIdx.x;
    if (b >= NB) return;
    const float* hp = hin + ((size_t)(NT - 1) * NB + b) * HID;
    float acc = b_fc[0];
#pragma unroll
    for (int k = 0; k < HID; k++) acc += hp[k] * w_fc[k];
    out[b] = acc;
}

// ---------------------------------------------------------------------------
extern "C" void kernel_launch(void* const* d_in, const int* in_sizes, int n_in,
                              void* d_out, int out_size) {
    const float* x     = (const float*)d_in[0];
    const float* w_ih0 = (const float*)d_in[1];
    const float* w_hh0 = (const float*)d_in[2];
    const float* b_ih0 = (const float*)d_in[3];
    const float* b_hh0 = (const float*)d_in[4];
    const float* w_ih  = (const float*)d_in[5];   // [4][192][64]
    const float* w_hh  = (const float*)d_in[6];   // [4][192][64]
    const float* b_ih  = (const float*)d_in[7];   // [4][192]
    const float* b_hh  = (const float*)d_in[8];   // [4][192]
    const float* w_fc  = (const float*)d_in[9];
    const float* b_fc  = (const float*)d_in[10];
    float* out = (float*)d_out;

    float *hA, *hB, *xgA, *xgB;
    cudaGetSymbolAddress((void**)&hA, g_h0);
    cudaGetSymbolAddress((void**)&hB, g_h1);
    cudaGetSymbolAddress((void**)&xgA, g_xgA);
    cudaGetSymbolAddress((void**)&xgB, g_xgB);

    // Layer 0 (scalar fp32 input GEMM + scan)
    k_inp0<<<(NT * NB) / 32, NG>>>(x, w_ih0, b_ih0, xgA);
    k_scan<<<NB / 2, 384>>>(w_hh0, b_hh0, xgA, hA, 1);

    // Layers 1..4: TF32 tensor-core input GEMM + fp32 scan
    float* hin = hA;
    float* hou = hB;
    for (int L = 0; L < 4; L++) {
        int last = (L == 3);
        float* xg = (L & 1) ? xgA : xgB;
        k_inp_tc<<<(NT * NB) / 128, 384>>>(hin, w_ih + (size_t)L * NG * HID,
                                           b_ih + L * NG, xg);
        k_scan<<<NB / 2, 384>>>(w_hh + (size_t)L * NG * HID, b_hh + L * NG,
                                xg, hou, !last);
        float* tmp = hin; hin = hou; hou = tmp;
    }

    // FC head on last timestep (hin holds the last layer's output)
    k_fc<<<2, 256>>>(hin, w_fc, b_fc, out);
}